// round 1
// baseline (speedup 1.0000x reference)
#include <cuda_runtime.h>
#include <math.h>

// Problem constants
#define H      2560
#define ESZ    2048
#define EPER   512
#define IPER   128
#define NB     64
#define NT     32
#define INSZ   128
#define NIN_ROWS 640      // rows receiving external input: E area0 (512) + I area0 (128)
#define KSPLIT 4

// Scratch (device globals: allocation-free rule)
__device__ float g_Weff[H * H];                 // |W_rec| * mask, row-major [h][k]
__device__ float g_P[KSPLIT * H * NB];          // K-split partials [kp][h][b]
__device__ float g_Iin[NT * NIN_ROWS * NB];     // precomputed input drive [t][h'][b]
__device__ float g_state[H * NB];               // state, transposed [h][b]
__device__ float g_act0[NB * H];                // retanh(state0), layout [b][h] (matches d_out)

__device__ __forceinline__ int area_of(int u) {
    return u < ESZ ? (u >> 9) : ((u - ESZ) >> 7);
}

// ---------------------------------------------------------------------------
// Prep 1: effective recurrent weights Weff = |W_rec| * sign * conn, diag = 0
// ---------------------------------------------------------------------------
__global__ void prep_weights(const float* __restrict__ Wrec) {
    int h = blockIdx.x;
    int ar = area_of(h);
    const float* src = Wrec + h * H;
    float* dst = g_Weff + h * H;
    for (int k = threadIdx.x; k < H; k += blockDim.x) {
        int conn; float sgn;
        if (k < ESZ) {
            int d = ar - (k >> 9);
            conn = (d >= -1 && d <= 1);
            sgn = 1.0f;
        } else {
            conn = ((k - ESZ) >> 7) == ar;
            sgn = -1.0f;
        }
        float m = (conn && (h != k)) ? sgn : 0.0f;
        dst[k] = fabsf(src[k]) * m;
    }
}

// ---------------------------------------------------------------------------
// Prep 2: state buffer (transposed) + initial activation
// ---------------------------------------------------------------------------
__global__ void prep_state(const float* __restrict__ state0) {
    int idx = blockIdx.x * blockDim.x + threadIdx.x;
    if (idx >= NB * H) return;
    int b = idx / H, h = idx % H;
    float s = state0[idx];
    g_state[h * NB + b] = s;
    g_act0[idx] = tanhf(fmaxf(s, 0.0f));
}

// ---------------------------------------------------------------------------
// Prep 3: input drive for ALL timesteps at once:
//   Iin[t][h'][b] = sum_k relu(x[t][b][k]) * |W_in[h][k]|   (area-0 rows only)
// grid = (40 h'-tiles of 16, 32 t), 256 threads: thread = (b, 4 h')
// ---------------------------------------------------------------------------
__global__ void prep_input(const float* __restrict__ x, const float* __restrict__ Win) {
    int t   = blockIdx.y;
    int hp0 = blockIdx.x * 16;
    __shared__ float xS[64 * 133];   // [b][k], pad 133 -> conflict-free strided reads
    __shared__ float wS[16 * 128];

    for (int r = threadIdx.x; r < 64 * 128; r += blockDim.x) {
        int bb = r >> 7, kk = r & 127;
        xS[bb * 133 + kk] = fmaxf(x[t * (NB * INSZ) + r], 0.0f);
    }
    for (int r = threadIdx.x; r < 16 * 128; r += blockDim.x) {
        int i = r >> 7, kk = r & 127;
        int hp = hp0 + i;
        int h  = (hp < EPER) ? hp : (ESZ + (hp - EPER));
        wS[r] = fabsf(Win[h * INSZ + kk]);
    }
    __syncthreads();

    int b  = threadIdx.x & 63;
    int hq = threadIdx.x >> 6;   // 0..3
    float acc[4] = {0.f, 0.f, 0.f, 0.f};
    for (int k = 0; k < 128; ++k) {
        float xv = xS[b * 133 + k];
#pragma unroll
        for (int j = 0; j < 4; ++j)
            acc[j] = fmaf(xv, wS[(hq * 4 + j) * 128 + k], acc[j]);
    }
#pragma unroll
    for (int j = 0; j < 4; ++j) {
        int hp = hp0 + hq * 4 + j;
        g_Iin[(t * NIN_ROWS + hp) * NB + b] = acc[j];
    }
}

// ---------------------------------------------------------------------------
// Step kernel A: block-sparse partial GEMM.
//   P[kp][h][b] = sum_{k in quarter of h's K-range} act[b][k] * Weff[h][k]
// grid = (80 h-tiles of 32, KSPLIT), 128 threads, 4b x 4h register tiles.
// act = d_out[t-1] (== retanh(state_t)) or g_act0 at t==0.  Layout [b][H].
// ---------------------------------------------------------------------------
__global__ void __launch_bounds__(128) step_partial(const float* __restrict__ out, int t) {
    const float* act = (t == 0) ? g_act0 : (out + (t - 1) * NB * H);

    int h0 = blockIdx.x * 32;
    int kp = blockIdx.y;
    int area = area_of(h0);
    int k0E  = (area > 0 ? area - 1 : 0) * EPER;
    int k1E  = ((area < 3 ? area + 1 : 3) + 1) * EPER;
    int lenE = k1E - k0E;
    int k0I  = ESZ + area * IPER;
    int partLen = (lenE + IPER) >> 2;          // 288 or 416, both % 32 == 0
    int offBeg = kp * partLen, offEnd = offBeg + partLen;

    __shared__ float actS[32 * 64];            // [k][b], XOR-swizzled quads
    __shared__ float wS[32 * 33];              // [h_local][k], pad 33

    int tx = threadIdx.x & 15;                 // b-quad
    int ty = threadIdx.x >> 4;                 // h-quad (0..7)

    float acc[4][4];
#pragma unroll
    for (int j = 0; j < 4; ++j)
#pragma unroll
        for (int i = 0; i < 4; ++i) acc[j][i] = 0.f;

    for (int off = offBeg; off < offEnd; off += 32) {
        int kg = (off < lenE) ? (k0E + off) : (k0I + (off - lenE));

        // --- stage act chunk [32k x 64b], transpose with XOR swizzle ---
        {
            int kq = threadIdx.x & 7;          // k-quad within chunk
            int bb = threadIdx.x >> 3;         // 0..15
#pragma unroll
            for (int r = 0; r < 4; ++r) {
                int b = bb + (r << 4);
                float4 v = *reinterpret_cast<const float4*>(&act[b * H + kg + kq * 4]);
                int bq = b >> 2, bl = b & 3;
                float vv[4] = {v.x, v.y, v.z, v.w};
#pragma unroll
                for (int i = 0; i < 4; ++i) {
                    int k = kq * 4 + i;
                    int s = ((k >> 2) ^ k) & 15;           // swizzle
                    actS[k * 64 + ((bq ^ s) << 2) + bl] = vv[i];
                }
            }
        }
        // --- stage weight chunk [32h x 32k] ---
#pragma unroll
        for (int r = 0; r < 8; ++r) {
            int flat = threadIdx.x + (r << 7);
            int kk = flat & 31, i = flat >> 5;
            wS[i * 33 + kk] = g_Weff[(h0 + i) * H + kg + kk];
        }
        __syncthreads();

#pragma unroll 8
        for (int k = 0; k < 32; ++k) {
            int s = ((k >> 2) ^ k) & 15;
            float4 a = *reinterpret_cast<const float4*>(&actS[k * 64 + ((tx ^ s) << 2)]);
#pragma unroll
            for (int j = 0; j < 4; ++j) {
                float w = wS[(ty * 4 + j) * 33 + k];
                acc[j][0] = fmaf(a.x, w, acc[j][0]);
                acc[j][1] = fmaf(a.y, w, acc[j][1]);
                acc[j][2] = fmaf(a.z, w, acc[j][2]);
                acc[j][3] = fmaf(a.w, w, acc[j][3]);
            }
        }
        __syncthreads();
    }

#pragma unroll
    for (int j = 0; j < 4; ++j) {
        int h = h0 + ty * 4 + j;
        float4 v = make_float4(acc[j][0], acc[j][1], acc[j][2], acc[j][3]);
        *reinterpret_cast<float4*>(&g_P[(kp * H + h) * NB + tx * 4]) = v;
    }
}

// ---------------------------------------------------------------------------
// Step kernel B: reduce partials + bias + input drive, leaky update, retanh,
// write state and d_out[t].  grid = 160 (16h tiles), 256 threads.
// ---------------------------------------------------------------------------
__global__ void step_update(const float* __restrict__ b_rec, float* __restrict__ out, int t) {
    int h0 = blockIdx.x * 16;
    bool hasIn = (h0 < EPER) || (h0 >= ESZ && h0 < ESZ + IPER);
    int b  = threadIdx.x & 63;
    int hq = threadIdx.x >> 6;   // 0..3
    __shared__ float outS[16 * 65];

#pragma unroll
    for (int j = 0; j < 4; ++j) {
        int hl = hq * 4 + j;
        int h  = h0 + hl;
        float p = g_P[(0 * H + h) * NB + b] + g_P[(1 * H + h) * NB + b]
                + g_P[(2 * H + h) * NB + b] + g_P[(3 * H + h) * NB + b];
        p += b_rec[h];
        if (hasIn) {
            int hp = (h < EPER) ? h : (EPER + (h - ESZ));
            p += g_Iin[(t * NIN_ROWS + hp) * NB + b];
        }
        float s  = g_state[h * NB + b];
        float ns = s * 0.8f + 0.2f * p;
        g_state[h * NB + b] = ns;
        outS[hl * 65 + b] = tanhf(fmaxf(ns, 0.0f));
    }
    __syncthreads();

    // coalesced-ish output write via smem transpose
    int b2 = threadIdx.x >> 2;   // 0..63
    int jq = threadIdx.x & 3;    // 0..3
    float4 v;
    v.x = outS[(jq * 4 + 0) * 65 + b2];
    v.y = outS[(jq * 4 + 1) * 65 + b2];
    v.z = outS[(jq * 4 + 2) * 65 + b2];
    v.w = outS[(jq * 4 + 3) * 65 + b2];
    *reinterpret_cast<float4*>(&out[(t * NB + b2) * H + h0 + jq * 4]) = v;
}

// ---------------------------------------------------------------------------
extern "C" void kernel_launch(void* const* d_in, const int* in_sizes, int n_in,
                              void* d_out, int out_size) {
    (void)in_sizes; (void)n_in; (void)out_size;
    const float* x      = (const float*)d_in[0];   // [32, 64, 128]
    const float* W_in   = (const float*)d_in[1];   // [2560, 128]
    const float* W_rec  = (const float*)d_in[2];   // [2560, 2560]
    const float* b_rec  = (const float*)d_in[3];   // [2560]
    const float* state0 = (const float*)d_in[4];   // [64, 2560]
    float* out = (float*)d_out;                    // [32, 64, 2560]

    prep_weights<<<H, 256>>>(W_rec);
    prep_state<<<(NB * H + 255) / 256, 256>>>(state0);
    prep_input<<<dim3(NIN_ROWS / 16, NT), 256>>>(x, W_in);

    for (int t = 0; t < NT; ++t) {
        step_partial<<<dim3(H / 32, KSPLIT), 128>>>(out, t);
        step_update<<<H / 16, 256>>>(b_rec, out, t);
    }
}

// round 2
// speedup vs baseline: 1.0547x; 1.0547x over previous
#include <cuda_runtime.h>
#include <math.h>

// Problem constants
#define H      2560
#define ESZ    2048
#define EPER   512
#define IPER   128
#define NB     64
#define NT     32
#define INSZ   128
#define NIN_ROWS 640
#define KS     8          // K-split (round-robin chunks of 32)

// Scratch (device globals: allocation-free rule)
__device__ float g_WeffT[H * H];                // |W_rec|*mask, TRANSPOSED: [k][h]
__device__ float g_P[KS * H * NB];              // K-split partials [kp][h][b]
__device__ float g_Iin[NT * NIN_ROWS * NB];     // precomputed input drive [t][h'][b]
__device__ float g_state[H * NB];               // state, [h][b]
__device__ float g_actT[H * NB];                // retanh(state_t), [h][b]

__device__ __forceinline__ int area_of(int u) {
    return u < ESZ ? (u >> 9) : ((u - ESZ) >> 7);
}

union UF2 { unsigned long long u; float2 f; };

__device__ __forceinline__ void ffma2(unsigned long long& d,
                                      unsigned long long a,
                                      unsigned long long b) {
    asm("fma.rn.f32x2 %0, %1, %2, %0;" : "+l"(d) : "l"(a), "l"(b));
}
__device__ __forceinline__ unsigned long long dup2(float w) {
    unsigned long long r;
    asm("mov.b64 %0, {%1, %1};" : "=l"(r) : "r"(__float_as_uint(w)));
    return r;
}

// ---------------------------------------------------------------------------
// Prep 1: WeffT[k][h] = |W_rec[h][k]| * sign(k) * conn(h,k), diag 0.
// Tiled transpose, 32x32 tiles, coalesced both sides.
// ---------------------------------------------------------------------------
__global__ void prep_weights(const float* __restrict__ Wrec) {
    __shared__ float tS[32][33];
    int h0 = blockIdx.x * 32, k0 = blockIdx.y * 32;
    int tid = threadIdx.x;                 // 128 threads
    for (int r = 0; r < 8; ++r) {
        int flat = tid + r * 128;          // 0..1023
        int i = flat >> 5, kk = flat & 31; // h-local, k-local
        int h = h0 + i, k = k0 + kk;
        int ar = area_of(h);
        int conn; float sgn;
        if (k < ESZ) { int d = ar - (k >> 9); conn = (d >= -1 && d <= 1); sgn = 1.0f; }
        else         { conn = ((k - ESZ) >> 7) == ar;                     sgn = -1.0f; }
        float m = (conn && (h != k)) ? sgn : 0.0f;
        tS[kk][i] = fabsf(Wrec[h * H + k]) * m;
    }
    __syncthreads();
    for (int r = 0; r < 8; ++r) {
        int flat = tid + r * 128;
        int kk = flat >> 5, i = flat & 31;
        g_WeffT[(k0 + kk) * H + h0 + i] = tS[kk][i];
    }
}

// ---------------------------------------------------------------------------
// Prep 2: state [h][b] + initial activation [h][b]
// ---------------------------------------------------------------------------
__global__ void prep_state(const float* __restrict__ state0) {
    int idx = blockIdx.x * blockDim.x + threadIdx.x;
    if (idx >= NB * H) return;
    int b = idx / H, h = idx % H;
    float s = state0[idx];
    g_state[h * NB + b] = s;
    g_actT[h * NB + b] = tanhf(fmaxf(s, 0.0f));
}

// ---------------------------------------------------------------------------
// Prep 3: input drive for all timesteps (area-0 rows only)
// ---------------------------------------------------------------------------
__global__ void prep_input(const float* __restrict__ x, const float* __restrict__ Win) {
    int t   = blockIdx.y;
    int hp0 = blockIdx.x * 16;
    __shared__ float xS[64 * 133];
    __shared__ float wS[16 * 128];

    for (int r = threadIdx.x; r < 64 * 128; r += blockDim.x) {
        int bb = r >> 7, kk = r & 127;
        xS[bb * 133 + kk] = fmaxf(x[t * (NB * INSZ) + r], 0.0f);
    }
    for (int r = threadIdx.x; r < 16 * 128; r += blockDim.x) {
        int i = r >> 7, kk = r & 127;
        int hp = hp0 + i;
        int h  = (hp < EPER) ? hp : (ESZ + (hp - EPER));
        wS[r] = fabsf(Win[h * INSZ + kk]);
    }
    __syncthreads();

    int b  = threadIdx.x & 63;
    int hq = threadIdx.x >> 6;
    float acc[4] = {0.f, 0.f, 0.f, 0.f};
    for (int k = 0; k < 128; ++k) {
        float xv = xS[b * 133 + k];
#pragma unroll
        for (int j = 0; j < 4; ++j)
            acc[j] = fmaf(xv, wS[(hq * 4 + j) * 128 + k], acc[j]);
    }
#pragma unroll
    for (int j = 0; j < 4; ++j)
        g_Iin[(t * NIN_ROWS + hp0 + hq * 4 + j) * NB + b] = acc[j];
}

// ---------------------------------------------------------------------------
// Step kernel A: block-sparse partial GEMM with packed f32x2 FMA.
//   Tile: 64h x 64b, 128 threads, 4h x 8b per thread (accs as 4h x 4 b-pairs).
//   grid = (H/64=40, KS=8); chunk c (32 k) handled by kp == c % KS (round robin).
//   act source: g_actT [k][b] (contiguous chunks). weights: g_WeffT [k][h].
// ---------------------------------------------------------------------------
__global__ void __launch_bounds__(128) step_partial() {
    const int h0 = blockIdx.x * 64;
    const int kp = blockIdx.y;
    const int area = area_of(h0);
    const int aE0 = (area > 0 ? area - 1 : 0);
    const int aE1 = (area < 3 ? area + 1 : 3);
    const int k0E = aE0 * EPER;
    const int lenE = (aE1 - aE0 + 1) * EPER;
    const int k0I = ESZ + area * IPER;
    const int nch = (lenE + IPER) >> 5;     // 36 or 52 chunks of 32

    __shared__ float actS[32 * 64];         // [k][b]
    __shared__ float wS[32 * 64];           // [k][h_local]

    const int tid = threadIdx.x;
    const int tx = tid & 7;                 // b-group (8 b each)
    const int ty = tid >> 3;                // h-group (4 h each), 0..15

    unsigned actS_u = (unsigned)__cvta_generic_to_shared(actS);
    unsigned wS_u   = (unsigned)__cvta_generic_to_shared(wS);

    unsigned long long acc[4][4];
#pragma unroll
    for (int j = 0; j < 4; ++j)
#pragma unroll
        for (int p = 0; p < 4; ++p) acc[j][p] = 0ull;

    float4 pa[4], pw[4];
    bool havePrefetch = false;

    for (int c = kp; c < nch; c += KS) {
        if (!havePrefetch) {
            int off = c * 32;
            int kg = (off < lenE) ? (k0E + off) : (k0I + (off - lenE));
            const float4* asrc = reinterpret_cast<const float4*>(g_actT + kg * 64);
#pragma unroll
            for (int r = 0; r < 4; ++r) pa[r] = asrc[tid + r * 128];
#pragma unroll
            for (int r = 0; r < 4; ++r) {
                int idx = tid + r * 128;
                int kk = idx >> 4, i2 = idx & 15;
                pw[r] = *reinterpret_cast<const float4*>(g_WeffT + (kg + kk) * H + h0 + i2 * 4);
            }
        }
        // stage prefetched chunk
#pragma unroll
        for (int r = 0; r < 4; ++r)
            reinterpret_cast<float4*>(actS)[tid + r * 128] = pa[r];
#pragma unroll
        for (int r = 0; r < 4; ++r) {
            int idx = tid + r * 128;
            int kk = idx >> 4, i2 = idx & 15;
            *reinterpret_cast<float4*>(wS + kk * 64 + i2 * 4) = pw[r];
        }
        __syncthreads();

        // prefetch next chunk (overlaps with compute)
        int cn = c + KS;
        havePrefetch = (cn < nch);
        if (havePrefetch) {
            int off = cn * 32;
            int kg = (off < lenE) ? (k0E + off) : (k0I + (off - lenE));
            const float4* asrc = reinterpret_cast<const float4*>(g_actT + kg * 64);
#pragma unroll
            for (int r = 0; r < 4; ++r) pa[r] = asrc[tid + r * 128];
#pragma unroll
            for (int r = 0; r < 4; ++r) {
                int idx = tid + r * 128;
                int kk = idx >> 4, i2 = idx & 15;
                pw[r] = *reinterpret_cast<const float4*>(g_WeffT + (kg + kk) * H + h0 + i2 * 4);
            }
        }

        // compute: 32 k of 4h x 8b with FFMA2
#pragma unroll
        for (int k = 0; k < 32; ++k) {
            unsigned long long a0, a1, a2, a3;
            unsigned aaddr = actS_u + k * 256 + tx * 32;
            asm volatile("ld.shared.v2.b64 {%0,%1}, [%2];"
                         : "=l"(a0), "=l"(a1) : "r"(aaddr));
            asm volatile("ld.shared.v2.b64 {%0,%1}, [%2+16];"
                         : "=l"(a2), "=l"(a3) : "r"(aaddr));
            float4 w4;
            unsigned waddr = wS_u + k * 256 + ty * 16;
            asm volatile("ld.shared.v4.f32 {%0,%1,%2,%3}, [%4];"
                         : "=f"(w4.x), "=f"(w4.y), "=f"(w4.z), "=f"(w4.w) : "r"(waddr));
            unsigned long long w0 = dup2(w4.x), w1 = dup2(w4.y),
                               w2 = dup2(w4.z), w3 = dup2(w4.w);
            ffma2(acc[0][0], a0, w0); ffma2(acc[0][1], a1, w0);
            ffma2(acc[0][2], a2, w0); ffma2(acc[0][3], a3, w0);
            ffma2(acc[1][0], a0, w1); ffma2(acc[1][1], a1, w1);
            ffma2(acc[1][2], a2, w1); ffma2(acc[1][3], a3, w1);
            ffma2(acc[2][0], a0, w2); ffma2(acc[2][1], a1, w2);
            ffma2(acc[2][2], a2, w2); ffma2(acc[2][3], a3, w2);
            ffma2(acc[3][0], a0, w3); ffma2(acc[3][1], a1, w3);
            ffma2(acc[3][2], a2, w3); ffma2(acc[3][3], a3, w3);
        }
        __syncthreads();
    }

    // write partials: P[kp][h][b], 8 consecutive b per thread
#pragma unroll
    for (int j = 0; j < 4; ++j) {
        int h = h0 + ty * 4 + j;
        UF2 u0, u1, u2, u3;
        u0.u = acc[j][0]; u1.u = acc[j][1]; u2.u = acc[j][2]; u3.u = acc[j][3];
        float* dst = g_P + (kp * H + h) * NB + tx * 8;
        *reinterpret_cast<float4*>(dst)     = make_float4(u0.f.x, u0.f.y, u1.f.x, u1.f.y);
        *reinterpret_cast<float4*>(dst + 4) = make_float4(u2.f.x, u2.f.y, u3.f.x, u3.f.y);
    }
}

// ---------------------------------------------------------------------------
// Step kernel B: reduce KS partials + bias + input, leaky update, retanh.
// Writes g_state [h][b], g_actT [h][b] (next step's GEMM input), out[t][b][h].
// ---------------------------------------------------------------------------
__global__ void step_update(const float* __restrict__ b_rec, float* __restrict__ out, int t) {
    int h0 = blockIdx.x * 16;
    bool hasIn = (h0 < EPER) || (h0 >= ESZ && h0 < ESZ + IPER);
    int b  = threadIdx.x & 63;
    int hq = threadIdx.x >> 6;
    __shared__ float outS[16 * 65];

#pragma unroll
    for (int j = 0; j < 4; ++j) {
        int hl = hq * 4 + j;
        int h  = h0 + hl;
        float p = 0.f;
#pragma unroll
        for (int kp = 0; kp < KS; ++kp)
            p += g_P[(kp * H + h) * NB + b];
        p += b_rec[h];
        if (hasIn) {
            int hp = (h < EPER) ? h : (EPER + (h - ESZ));
            p += g_Iin[(t * NIN_ROWS + hp) * NB + b];
        }
        float s  = g_state[h * NB + b];
        float ns = s * 0.8f + 0.2f * p;
        g_state[h * NB + b] = ns;
        float a = tanhf(fmaxf(ns, 0.0f));
        g_actT[h * NB + b] = a;
        outS[hl * 65 + b] = a;
    }
    __syncthreads();

    int b2 = threadIdx.x >> 2;
    int jq = threadIdx.x & 3;
    float4 v;
    v.x = outS[(jq * 4 + 0) * 65 + b2];
    v.y = outS[(jq * 4 + 1) * 65 + b2];
    v.z = outS[(jq * 4 + 2) * 65 + b2];
    v.w = outS[(jq * 4 + 3) * 65 + b2];
    *reinterpret_cast<float4*>(&out[(t * NB + b2) * H + h0 + jq * 4]) = v;
}

// ---------------------------------------------------------------------------
extern "C" void kernel_launch(void* const* d_in, const int* in_sizes, int n_in,
                              void* d_out, int out_size) {
    (void)in_sizes; (void)n_in; (void)out_size;
    const float* x      = (const float*)d_in[0];
    const float* W_in   = (const float*)d_in[1];
    const float* W_rec  = (const float*)d_in[2];
    const float* b_rec  = (const float*)d_in[3];
    const float* state0 = (const float*)d_in[4];
    float* out = (float*)d_out;

    prep_weights<<<dim3(H / 32, H / 32), 128>>>(W_rec);
    prep_state<<<(NB * H + 255) / 256, 256>>>(state0);
    prep_input<<<dim3(NIN_ROWS / 16, NT), 256>>>(x, W_in);

    for (int t = 0; t < NT; ++t) {
        step_partial<<<dim3(H / 64, KS), 128>>>();
        step_update<<<H / 16, 256>>>(b_rec, out, t);
    }
}